// round 9
// baseline (speedup 1.0000x reference)
#include <cuda_runtime.h>
#include <cuda_bf16.h>

#define BB 2
#define NN 16384
#define PP 4096
#define CC 64
#define SS 32
#define CH (3 + CC)   // 67
#define GC 10
#define NCELL (GC*GC*GC)
#define HB 320        // per-warp hit buffer capacity (multiple of 4)

// ---- scratch (__device__ globals; no cudaMalloc allowed) ----
__device__ float4 g_xyz4[BB * NN];           // packed xyz, .w = cell id
__device__ float  g_ftrt[BB * NN * CC];      // features transposed to (B,N,C)
__device__ float4 g_pts [BB * NN];           // cell-sorted points, .w = idx
__device__ int    g_start[BB * (NCELL + 1)]; // exclusive scan
__device__ int    g_idx [BB * PP * SS];      // ball query result

__device__ __forceinline__ int cell_of(float x, float y, float z) {
    int cx = min((int)(x * 10.0f), GC - 1);
    int cy = min((int)(y * 10.0f), GC - 1);
    int cz = min((int)(z * 10.0f), GC - 1);
    return (cz * GC + cy) * GC + cx;
}

// ---------------------------------------------------------------------------
// Whole grid build in ONE kernel: one 1024-thread block per batch.
//  A: pack xyz->float4(+cell), histogram in SMEM (fast atomics)
//  B: exclusive scan of 1000 counts in SMEM; publish g_start; hist -> cursor
//  C: scatter into cell-sorted g_pts via SMEM cursor atomics
// ---------------------------------------------------------------------------
__global__ void __launch_bounds__(1024) build_kernel(const float* __restrict__ xyz) {
    __shared__ int hist[NCELL];
    __shared__ int wsum[32];
    int b   = blockIdx.x;
    int tid = threadIdx.x;
    int lane = tid & 31, wid = tid >> 5;

    if (tid < NCELL) hist[tid] = 0;
    __syncthreads();

    // ---- A: pack + count (4 points/thread/group, 4 groups) ----
#pragma unroll
    for (int g = 0; g < 4; g++) {
        int i0 = (g * 1024 + tid) * 4;                 // batch-local
        const float4* src = (const float4*)(xyz + ((size_t)b * NN + i0) * 3);
        float4 a = src[0], b4 = src[1], c4 = src[2];
        float px[4] = {a.x, a.w,  b4.z, c4.y};
        float py[4] = {a.y, b4.x, b4.w, c4.z};
        float pz[4] = {a.z, b4.y, c4.x, c4.w};
#pragma unroll
        for (int k = 0; k < 4; k++) {
            int cell = cell_of(px[k], py[k], pz[k]);
            g_xyz4[(size_t)b * NN + i0 + k] =
                make_float4(px[k], py[k], pz[k], __int_as_float(cell));
            atomicAdd(&hist[cell], 1);
        }
    }
    __syncthreads();

    // ---- B: exclusive scan (each thread touches only its own slot) ----
    int v = (tid < NCELL) ? hist[tid] : 0;
    int s = v;
#pragma unroll
    for (int o = 1; o < 32; o <<= 1) {
        int u = __shfl_up_sync(0xffffffffu, s, o);
        if (lane >= o) s += u;
    }
    if (lane == 31) wsum[wid] = s;
    __syncthreads();
    if (wid == 0) {
        int ws = wsum[lane];
#pragma unroll
        for (int o = 1; o < 32; o <<= 1) {
            int u = __shfl_up_sync(0xffffffffu, ws, o);
            if (lane >= o) ws += u;
        }
        wsum[lane] = ws;
    }
    __syncthreads();
    int incl = s + (wid ? wsum[wid - 1] : 0);
    if (tid < NCELL) {
        hist[tid] = incl - v;                          // cursor = exclusive
        g_start[b * (NCELL + 1) + tid + 1] = incl;
    }
    if (tid == 0) g_start[b * (NCELL + 1)] = 0;
    __syncthreads();

    // ---- C: scatter (SMEM cursor atomics; g_xyz4 is L1/L2-hot) ----
#pragma unroll
    for (int g = 0; g < 4; g++) {
        int i0 = (g * 1024 + tid) * 4;
#pragma unroll
        for (int k = 0; k < 4; k++) {
            float4 p = g_xyz4[(size_t)b * NN + i0 + k];
            int c   = __float_as_int(p.w);
            int pos = atomicAdd(&hist[c], 1);
            g_pts[(size_t)b * NN + pos] =
                make_float4(p.x, p.y, p.z, __int_as_float(i0 + k));
        }
    }
}

// ---------------------------------------------------------------------------
// Fused: grid ball query (compute-bound) + feature transpose (memory-bound).
// Query: per-row x-pruned cell scan (conservative over-include; exact frozen
// distance test decides). Rank: all-pairs vs buffer, int4 LDS.128 loads,
// all of a lane's ranks in ONE pass (warp-uniform K variants).
// ---------------------------------------------------------------------------
#define QBLK ((BB * PP) / 8)                // 1024 query blocks
#define TBLK ((NN / 32) * (CC / 32) * BB)   // 2048 transpose blocks

__global__ void __launch_bounds__(256) query_transpose_kernel(
        const float* __restrict__ new_xyz, const float* __restrict__ f) {
    __shared__ union {
        int   hb[8][HB];            // query: per-warp hit buffers
        float tile[32][33];         // transpose tile
    } sm;

    int bx = blockIdx.x;
    if (bx >= QBLK) {
        // ---- transpose part: 32ch x 32pts tile, fully vectorized ----
        int r  = bx - QBLK;
        int nt = NN / 32;
        int b  = r / (nt * 2);
        int rr = r % (nt * 2);
        int c0 = (rr / nt) * 32;
        int n0 = (rr % nt) * 32;
        int t  = threadIdx.x;
        {
            int c = t >> 3, n4 = t & 7;
            float4 v = *(const float4*)(f + ((size_t)b * CC + c0 + c) * NN
                                          + n0 + n4 * 4);
            sm.tile[c][n4 * 4 + 0] = v.x;
            sm.tile[c][n4 * 4 + 1] = v.y;
            sm.tile[c][n4 * 4 + 2] = v.z;
            sm.tile[c][n4 * 4 + 3] = v.w;
        }
        __syncthreads();
        {
            int n = t >> 3, c4 = t & 7;
            float4 v;
            v.x = sm.tile[c4 * 4 + 0][n];
            v.y = sm.tile[c4 * 4 + 1][n];
            v.z = sm.tile[c4 * 4 + 2][n];
            v.w = sm.tile[c4 * 4 + 3][n];
            *(float4*)(g_ftrt + ((size_t)b * NN + n0 + n) * CC + c0 + c4 * 4) = v;
        }
        return;
    }

    // ---- query part ----
    int w    = (bx * blockDim.x + threadIdx.x) >> 5;
    int lane = threadIdx.x & 31;
    int b = w / PP;
    int* buf = sm.hb[(threadIdx.x >> 5) & 7];

    float qx = new_xyz[3 * w + 0];
    float qy = new_xyz[3 * w + 1];
    float qz = new_xyz[3 * w + 2];
    int cx = min((int)(qx * 10.0f), GC - 1);
    int cy = min((int)(qy * 10.0f), GC - 1);
    int cz = min((int)(qz * 10.0f), GC - 1);

    const int*    st  = g_start + b * (NCELL + 1);
    const float4* pts = g_pts + (size_t)b * NN;

    int K = 0;
#pragma unroll
    for (int dz = -1; dz <= 1; dz++) {
        int z = cz + dz;
        if (z < 0 || z >= GC) continue;
        float dzf = (dz == 0) ? 0.0f
                  : (dz < 0 ? qz - (float)cz * 0.1f
                            : (float)(cz + 1) * 0.1f - qz);
        float dz2 = dzf * dzf;
#pragma unroll
        for (int dy = -1; dy <= 1; dy++) {
            int y = cy + dy;
            if (y < 0 || y >= GC) continue;
            float dyf = (dy == 0) ? 0.0f
                      : (dy < 0 ? qy - (float)cy * 0.1f
                                : (float)(cy + 1) * 0.1f - qy);
            float rem = 0.01f + 3e-8f - dz2 - dyf * dyf;
            if (rem <= 0.0f) continue;                 // row can't reach ball
            float dxm = __fsqrt_ru(rem);
            int x0 = max((int)((qx - dxm) * 10.0f - 1e-5f), 0);
            int x1 = min((int)((qx + dxm) * 10.0f + 1e-5f), GC - 1);
            int row = (z * GC + y) * GC;
            int rs = st[row + x0];
            int re = st[row + x1 + 1];
            for (int base = rs; base < re; base += 32) {
                int j = base + lane;
                bool hit = false; int id = 0;
                if (j < re) {
                    float4 pt = pts[j];
                    float ddx = qx - pt.x, ddy = qy - pt.y, ddz = qz - pt.z;
                    float d2 = __fmaf_rn(ddz, ddz,
                               __fmaf_rn(ddy, ddy, __fmul_rn(ddx, ddx)));
                    hit = d2 < 0.01f;
                    id  = __float_as_int(pt.w);
                }
                unsigned m = __ballot_sync(0xffffffffu, hit);
                if (hit) {
                    int pos = K + __popc(m & ((1u << lane) - 1u));
                    if (pos < HB) buf[pos] = id;
                }
                K += __popc(m);
            }
        }
    }
    if (K > HB) K = HB;
    int K4 = (K + 3) & ~3;
    if (lane < K4 - K) buf[K + lane] = 0x7fffffff;     // pad (never "smaller")
    __syncwarp();

    int* out = g_idx + (size_t)w * SS;
    int cnt  = min(K, SS);
    int padv = 0x7fffffff;
    const int4* buf4 = (const int4*)buf;
    int nq = K4 >> 2;

    // Rank = #{u: buf[u] < v}; deterministic (values only). One pass per warp.
    if (K <= 32) {
        int v0 = (lane < K) ? buf[lane] : 0x7fffffff;
        int r0 = 0;
        for (int u = 0; u < nq; u++) {
            int4 q = buf4[u];
            r0 += (q.x < v0) + (q.y < v0) + (q.z < v0) + (q.w < v0);
        }
        if (lane < K && r0 < SS) out[r0] = v0;
        padv = v0;
    } else if (K <= 64) {
        int v0 = buf[lane];
        int v1 = (32 + lane < K) ? buf[32 + lane] : 0x7fffffff;
        int r0 = 0, r1 = 0;
        for (int u = 0; u < nq; u++) {
            int4 q = buf4[u];
            r0 += (q.x < v0) + (q.y < v0) + (q.z < v0) + (q.w < v0);
            r1 += (q.x < v1) + (q.y < v1) + (q.z < v1) + (q.w < v1);
        }
        if (r0 < SS) out[r0] = v0;
        if (32 + lane < K && r1 < SS) out[r1] = v1;
        padv = min(v0, v1);
    } else if (K <= 96) {
        int v0 = buf[lane];
        int v1 = buf[32 + lane];
        int v2 = (64 + lane < K) ? buf[64 + lane] : 0x7fffffff;
        int r0 = 0, r1 = 0, r2 = 0;
        for (int u = 0; u < nq; u++) {
            int4 q = buf4[u];
            r0 += (q.x < v0) + (q.y < v0) + (q.z < v0) + (q.w < v0);
            r1 += (q.x < v1) + (q.y < v1) + (q.z < v1) + (q.w < v1);
            r2 += (q.x < v2) + (q.y < v2) + (q.z < v2) + (q.w < v2);
        }
        if (r0 < SS) out[r0] = v0;
        if (r1 < SS) out[r1] = v1;
        if (64 + lane < K && r2 < SS) out[r2] = v2;
        padv = min(min(v0, v1), v2);
    } else if (K <= 128) {
        int v0 = buf[lane];
        int v1 = buf[32 + lane];
        int v2 = buf[64 + lane];
        int v3 = (96 + lane < K) ? buf[96 + lane] : 0x7fffffff;
        int r0 = 0, r1 = 0, r2 = 0, r3 = 0;
        for (int u = 0; u < nq; u++) {
            int4 q = buf4[u];
            r0 += (q.x < v0) + (q.y < v0) + (q.z < v0) + (q.w < v0);
            r1 += (q.x < v1) + (q.y < v1) + (q.z < v1) + (q.w < v1);
            r2 += (q.x < v2) + (q.y < v2) + (q.z < v2) + (q.w < v2);
            r3 += (q.x < v3) + (q.y < v3) + (q.z < v3) + (q.w < v3);
        }
        if (r0 < SS) out[r0] = v0;
        if (r1 < SS) out[r1] = v1;
        if (r2 < SS) out[r2] = v2;
        if (96 + lane < K && r3 < SS) out[r3] = v3;
        padv = min(min(v0, v1), min(v2, v3));
    } else {
        // fallback: any K up to HB
        int G = (K + 31) >> 5;
        for (int g = 0; g < G; g++) {
            int t = g * 32 + lane;
            bool val = t < K;
            int v = val ? buf[t] : 0x7fffffff;
            int r = 0;
            for (int u = 0; u < nq; u++) {
                int4 q = buf4[u];
                r += (q.x < v) + (q.y < v) + (q.z < v) + (q.w < v);
            }
            if (val && r < SS) out[r] = v;
            padv = min(padv, v);
        }
    }
#pragma unroll
    for (int o = 16; o; o >>= 1)
        padv = min(padv, __shfl_xor_sync(0xffffffffu, padv, o));
    if (K == 0) padv = 0;
    if (lane >= cnt) out[lane] = padv;       // pad with first (= min index)
}

// ---------------------------------------------------------------------------
// Grouping: one warp per query; features gathered in two 32-channel halves
// staged through a [32][33] smem tile (both phases bank-conflict-free).
// ---------------------------------------------------------------------------
__global__ void __launch_bounds__(128) group_kernel(
        const float* __restrict__ new_xyz, float* __restrict__ out) {
    __shared__ float stage[4][32][33];
    int w    = (blockIdx.x * blockDim.x + threadIdx.x) >> 5;
    int lane = threadIdx.x & 31;
    if (w >= BB * PP) return;
    int b = w / PP;
    int p = w % PP;
    float (*st)[33] = stage[(threadIdx.x >> 5) & 3];

    int i = g_idx[(size_t)w * SS + lane];

    float qx = new_xyz[3 * w + 0];
    float qy = new_xyz[3 * w + 1];
    float qz = new_xyz[3 * w + 2];

    float4 pt = g_xyz4[(size_t)b * NN + i];

    const size_t chStride = (size_t)PP * SS;
    size_t obase = (((size_t)b * CH) * PP + p) * SS + lane;

    out[obase + 0 * chStride] = pt.x - qx;
    out[obase + 1 * chStride] = pt.y - qy;
    out[obase + 2 * chStride] = pt.z - qz;

    int q = lane >> 3;            // quarter: which of 4 points this iter
    int c = lane & 7;             // 16B chunk within 128B half-row
#pragma unroll
    for (int h = 0; h < 2; h++) {           // channel halves 0..31 / 32..63
#pragma unroll
        for (int j = 0; j < 8; j++) {       // 8 iters x 4 points = 32 points
            int ptid = 4 * j + q;
            int ii = __shfl_sync(0xffffffffu, i, ptid);
            const float4* src = (const float4*)
                (g_ftrt + ((size_t)b * NN + ii) * CC + h * 32) + c;
            float4 v = *src;
            float* d = &st[ptid][c * 4];
            d[0] = v.x; d[1] = v.y; d[2] = v.z; d[3] = v.w;
        }
        __syncwarp();
        size_t fo = obase + (size_t)(3 + h * 32) * chStride;
#pragma unroll
        for (int ch = 0; ch < 32; ch++)
            out[fo + (size_t)ch * chStride] = st[lane][ch];
        __syncwarp();
    }
}

// ---------------------------------------------------------------------------
extern "C" void kernel_launch(void* const* d_in, const int* in_sizes, int n_in,
                              void* d_out, int out_size) {
    const float* xyz     = (const float*)d_in[0];   // (2,16384,3)
    const float* new_xyz = (const float*)d_in[1];   // (2,4096,3)
    const float* feat    = (const float*)d_in[2];   // (2,64,16384)
    float* out = (float*)d_out;                     // (2,67,4096,32)

    build_kernel<<<BB, 1024>>>(xyz);
    query_transpose_kernel<<<QBLK + TBLK, 256>>>(new_xyz, feat);
    group_kernel<<<(BB * PP) / 4, 128>>>(new_xyz, out);
}